// round 15
// baseline (speedup 1.0000x reference)
#include <cuda_runtime.h>
#include <cuda_bf16.h>

// Cubic B-spline activation, uniform knots t_k = k/69, p = 3.
// i = clamp(floor(x*69), 3, 65); s = x*69 - i. Per-interval cubic poly
// coefficients (uniform B-spline basis matrix), 3-FMA Horner per element.
//
// Table: 8x bank-group replicated (entry k, replica r at slot k*8+r); each
// lane reads replica lane&7 -> every LDS.128 gather runs at its 4-wavefront
// floor. Unconditional gather (predication saved no L1 bandwidth, R12).
//
// VPT=8 float4 per thread, all 8 LDG.128 front-batched (MLP_p1 = 8), each
// load carrying an L2::256B prefetch hint so the paired 128-B sector is
// already in L2 when its LDG issues -> read-latency exposure halves without
// spending registers or instructions.

#define NTAB 63  // valid i in [3,65] -> k = i-3 in [0,62]
#define NREP 8
#define THREADS 256
#define VPT 8    // float4 per thread

__device__ __forceinline__ float4 ldg_pf4(const float4* p) {
    float4 v;
    asm volatile("ld.global.nc.L2::256B.v4.f32 {%0,%1,%2,%3}, [%4];"
                 : "=f"(v.x), "=f"(v.y), "=f"(v.z), "=f"(v.w) : "l"(p));
    return v;
}
__device__ __forceinline__ void stg_cs4(float4* p, float4 v) {
    asm volatile("st.global.cs.v4.f32 [%0], {%1,%2,%3,%4};"
                 :: "l"(p), "f"(v.x), "f"(v.y), "f"(v.z), "f"(v.w) : "memory");
}

__device__ __forceinline__ float spline_eval(float xx, unsigned tab_base) {
    float u = xx * 69.0f;
    float f = floorf(u);
    float fc = fminf(fmaxf(f, 3.0f), 65.0f);   // clamp in float domain
    float s = u - fc;
    int k = __float2int_rn(fc) - 3;            // 0..62 (fc is integral)

    // Conflict-free gather: entry stride NREP*16 = 128 B keeps this lane's
    // bank group fixed (tab_base carries the lane's replica offset).
    float4 a;
    unsigned addr = tab_base + (unsigned)k * (NREP * 16u);
    asm volatile("ld.shared.v4.f32 {%0, %1, %2, %3}, [%4];"
                 : "=f"(a.x), "=f"(a.y), "=f"(a.z), "=f"(a.w)
                 : "r"(addr));

    // Horner: ((a3*s + a2)*s + a1)*s + a0
    float r = fmaf(a.w, s, a.z);
    r = fmaf(r, s, a.y);
    r = fmaf(r, s, a.x);
    return r;
}

__device__ __forceinline__ void fill_table(float4* tab, const float* __restrict__ coef,
                                           int tid, int nthreads) {
    const float inv6 = 1.0f / 6.0f;
    for (int e = tid; e < NTAB * NREP; e += nthreads) {
        int k = e >> 3;  // e / NREP
        float c0 = coef[k], c1 = coef[k + 1], c2 = coef[k + 2], c3 = coef[k + 3];
        float4 a;
        a.x = (c0 + 4.0f * c1 + c2) * inv6;              // a0
        a.y = (c2 - c0) * 0.5f;                          // a1
        a.z = (c0 - 2.0f * c1 + c2) * 0.5f;              // a2
        a.w = (c3 - 3.0f * c2 + 3.0f * c1 - c0) * inv6;  // a3
        tab[e] = a;
    }
}

__device__ __forceinline__ float4 eval4(float4 xv, unsigned tab_base) {
    float4 ov;
    ov.x = spline_eval(xv.x, tab_base);
    ov.y = spline_eval(xv.y, tab_base);
    ov.z = spline_eval(xv.z, tab_base);
    ov.w = spline_eval(xv.w, tab_base);
    return ov;
}

__global__ void __launch_bounds__(THREADS, 4)
spline_act_kernel(const float4* __restrict__ x,
                  const float* __restrict__ coef,
                  float4* __restrict__ out,
                  int nvec) {
    __shared__ float4 tab[NTAB * NREP];
    int tid = threadIdx.x;
    fill_table(tab, coef, tid, THREADS);
    __syncthreads();

    // Per-lane replica offset folded into the base address once.
    unsigned tab_base = (unsigned)__cvta_generic_to_shared(tab) + (tid & 7) * 16u;

    int base = blockIdx.x * (THREADS * VPT) + tid;

    if ((blockIdx.x + 1) * (THREADS * VPT) <= nvec) {
        // Fast path: full block. All VPT loads front-batched (MLP_p1 = VPT).
        float4 xv[VPT];
#pragma unroll
        for (int v = 0; v < VPT; v++) xv[v] = ldg_pf4(&x[base + v * THREADS]);
#pragma unroll
        for (int v = 0; v < VPT; v++)
            stg_cs4(&out[base + v * THREADS], eval4(xv[v], tab_base));
    } else {
#pragma unroll
        for (int v = 0; v < VPT; v++) {
            int idx = base + v * THREADS;
            if (idx < nvec) stg_cs4(&out[idx], eval4(ldg_pf4(&x[idx]), tab_base));
        }
    }
}

// Tail kernel for non-multiple-of-4 element counts (not expected here).
__global__ void spline_act_tail(const float* __restrict__ x,
                                const float* __restrict__ coef,
                                float* __restrict__ out,
                                int start, int n) {
    __shared__ float4 tab[NTAB * NREP];
    int tid = threadIdx.x;
    fill_table(tab, coef, tid, 256);
    __syncthreads();
    unsigned tab_base = (unsigned)__cvta_generic_to_shared(tab) + (tid & 7) * 16u;
    int idx = start + blockIdx.x * blockDim.x + tid;
    if (idx < n) out[idx] = spline_eval(x[idx], tab_base);
}

extern "C" void kernel_launch(void* const* d_in, const int* in_sizes, int n_in,
                              void* d_out, int out_size) {
    const float* x    = (const float*)d_in[0];
    const float* coef = (const float*)d_in[1];
    long long n = in_sizes[0];
    if (n_in >= 2 && in_sizes[0] < in_sizes[1]) {  // defensive swap
        coef = (const float*)d_in[0];
        x    = (const float*)d_in[1];
        n    = in_sizes[1];
    }

    int nvec = (int)(n / 4);
    if (nvec > 0) {
        int per_block = THREADS * VPT;
        int blocks = (nvec + per_block - 1) / per_block;
        spline_act_kernel<<<blocks, THREADS>>>((const float4*)x, coef,
                                               (float4*)d_out, nvec);
    }
    int rem = (int)(n - (long long)nvec * 4);
    if (rem > 0) {
        spline_act_tail<<<1, 256>>>(x, coef, (float*)d_out, nvec * 4, (int)n);
    }
}

// round 16
// speedup vs baseline: 1.0078x; 1.0078x over previous
#include <cuda_runtime.h>
#include <cuda_bf16.h>

// Cubic B-spline activation, uniform knots t_k = k/69, p = 3.
// i = clamp(floor(x*69), 3, 65); s = x*69 - i. Per-interval cubic poly
// coefficients (uniform B-spline basis matrix), 3-FMA Horner per element.
//
// Table: 8x bank-group replicated (entry k, replica r at slot k*8+r); each
// lane reads replica lane&7 -> every LDS.128 gather runs at its 4-wavefront
// floor. Unconditional gather (predication saved no L1 bandwidth, R12).
//
// VPT=8 float4 per thread, all 8 LDG.128 front-batched (MLP_p1 = 8), each
// load carrying an L2::256B prefetch hint so the paired 128-B sector is
// already in L2 when its LDG issues -> read-latency exposure halves without
// spending registers or instructions.

#define NTAB 63  // valid i in [3,65] -> k = i-3 in [0,62]
#define NREP 8
#define THREADS 256
#define VPT 8    // float4 per thread

__device__ __forceinline__ float4 ldg_pf4(const float4* p) {
    float4 v;
    asm volatile("ld.global.nc.L2::256B.v4.f32 {%0,%1,%2,%3}, [%4];"
                 : "=f"(v.x), "=f"(v.y), "=f"(v.z), "=f"(v.w) : "l"(p));
    return v;
}
__device__ __forceinline__ void stg_cs4(float4* p, float4 v) {
    asm volatile("st.global.cs.v4.f32 [%0], {%1,%2,%3,%4};"
                 :: "l"(p), "f"(v.x), "f"(v.y), "f"(v.z), "f"(v.w) : "memory");
}

__device__ __forceinline__ float spline_eval(float xx, unsigned tab_base) {
    float u = xx * 69.0f;
    float f = floorf(u);
    float fc = fminf(fmaxf(f, 3.0f), 65.0f);   // clamp in float domain
    float s = u - fc;
    int k = __float2int_rn(fc) - 3;            // 0..62 (fc is integral)

    // Conflict-free gather: entry stride NREP*16 = 128 B keeps this lane's
    // bank group fixed (tab_base carries the lane's replica offset).
    float4 a;
    unsigned addr = tab_base + (unsigned)k * (NREP * 16u);
    asm volatile("ld.shared.v4.f32 {%0, %1, %2, %3}, [%4];"
                 : "=f"(a.x), "=f"(a.y), "=f"(a.z), "=f"(a.w)
                 : "r"(addr));

    // Horner: ((a3*s + a2)*s + a1)*s + a0
    float r = fmaf(a.w, s, a.z);
    r = fmaf(r, s, a.y);
    r = fmaf(r, s, a.x);
    return r;
}

__device__ __forceinline__ void fill_table(float4* tab, const float* __restrict__ coef,
                                           int tid, int nthreads) {
    const float inv6 = 1.0f / 6.0f;
    for (int e = tid; e < NTAB * NREP; e += nthreads) {
        int k = e >> 3;  // e / NREP
        float c0 = coef[k], c1 = coef[k + 1], c2 = coef[k + 2], c3 = coef[k + 3];
        float4 a;
        a.x = (c0 + 4.0f * c1 + c2) * inv6;              // a0
        a.y = (c2 - c0) * 0.5f;                          // a1
        a.z = (c0 - 2.0f * c1 + c2) * 0.5f;              // a2
        a.w = (c3 - 3.0f * c2 + 3.0f * c1 - c0) * inv6;  // a3
        tab[e] = a;
    }
}

__device__ __forceinline__ float4 eval4(float4 xv, unsigned tab_base) {
    float4 ov;
    ov.x = spline_eval(xv.x, tab_base);
    ov.y = spline_eval(xv.y, tab_base);
    ov.z = spline_eval(xv.z, tab_base);
    ov.w = spline_eval(xv.w, tab_base);
    return ov;
}

__global__ void __launch_bounds__(THREADS, 4)
spline_act_kernel(const float4* __restrict__ x,
                  const float* __restrict__ coef,
                  float4* __restrict__ out,
                  int nvec) {
    __shared__ float4 tab[NTAB * NREP];
    int tid = threadIdx.x;
    fill_table(tab, coef, tid, THREADS);
    __syncthreads();

    // Per-lane replica offset folded into the base address once.
    unsigned tab_base = (unsigned)__cvta_generic_to_shared(tab) + (tid & 7) * 16u;

    int base = blockIdx.x * (THREADS * VPT) + tid;

    if ((blockIdx.x + 1) * (THREADS * VPT) <= nvec) {
        // Fast path: full block. All VPT loads front-batched (MLP_p1 = VPT).
        float4 xv[VPT];
#pragma unroll
        for (int v = 0; v < VPT; v++) xv[v] = ldg_pf4(&x[base + v * THREADS]);
#pragma unroll
        for (int v = 0; v < VPT; v++)
            stg_cs4(&out[base + v * THREADS], eval4(xv[v], tab_base));
    } else {
#pragma unroll
        for (int v = 0; v < VPT; v++) {
            int idx = base + v * THREADS;
            if (idx < nvec) stg_cs4(&out[idx], eval4(ldg_pf4(&x[idx]), tab_base));
        }
    }
}

// Tail kernel for non-multiple-of-4 element counts (not expected here).
__global__ void spline_act_tail(const float* __restrict__ x,
                                const float* __restrict__ coef,
                                float* __restrict__ out,
                                int start, int n) {
    __shared__ float4 tab[NTAB * NREP];
    int tid = threadIdx.x;
    fill_table(tab, coef, tid, 256);
    __syncthreads();
    unsigned tab_base = (unsigned)__cvta_generic_to_shared(tab) + (tid & 7) * 16u;
    int idx = start + blockIdx.x * blockDim.x + tid;
    if (idx < n) out[idx] = spline_eval(x[idx], tab_base);
}

extern "C" void kernel_launch(void* const* d_in, const int* in_sizes, int n_in,
                              void* d_out, int out_size) {
    const float* x    = (const float*)d_in[0];
    const float* coef = (const float*)d_in[1];
    long long n = in_sizes[0];
    if (n_in >= 2 && in_sizes[0] < in_sizes[1]) {  // defensive swap
        coef = (const float*)d_in[0];
        x    = (const float*)d_in[1];
        n    = in_sizes[1];
    }

    int nvec = (int)(n / 4);
    if (nvec > 0) {
        int per_block = THREADS * VPT;
        int blocks = (nvec + per_block - 1) / per_block;
        spline_act_kernel<<<blocks, THREADS>>>((const float4*)x, coef,
                                               (float4*)d_out, nvec);
    }
    int rem = (int)(n - (long long)nvec * 4);
    if (rem > 0) {
        spline_act_tail<<<1, 256>>>(x, coef, (float*)d_out, nvec * 4, (int)n);
    }
}